// round 12
// baseline (speedup 1.0000x reference)
#include <cuda_runtime.h>
#include <cuda_bf16.h>

// out[b,s,e] = W_e[e, tokens[b,s]] + W_p[s,e]
// tokens: (2,2048) int32, W_e: (1024,32000) f32, W_p: (2048,1024) f32
// out: (2,2048,1024) f32
//
// Streaming v6. v5 (R11: 28.4us kernel, DRAM 64%) proved the cp.async
// pipeline fixed the latency exposure. v6 closes the remaining gap:
//  - NSUB 4->8 (e-span 128, grid 125 bins x 8 spans = 1000 blocks): halves
//    the redundant per-block token scan (was issue 23%/alu 13%) and halves
//    pipeline startup/drain overhead per byte streamed.
//  - CAP 2048->512 + __launch_bounds__(256,6): smem 41->35KB, regs capped
//    -> 6 blocks/SM (occupancy 57%->75%), more concurrent DRAM streams.

#define B 2
#define S 2048
#define E 1024
#define V 32000
#define NTOK (B * S)       // 4096

#define V_TILE 256
#define NBINS (V / V_TILE) // 125
#define ET 16              // e-rows per subtile
#define NSUB 8             // subtiles per block -> e-span 128
#define ESPANS 8           // 8 spans x 128 = 1024 = E
#define SSTRIDE 260        // 16B-aligned rows -> conflict-free STS/cp.async
#define CAP 512            // hit-list capacity (bin avg ~33; fallback if exceeded)

#define CP_ASYNC16(dst, src) \
    asm volatile("cp.async.cg.shared.global [%0], [%1], 16;" \
                 :: "r"(dst), "l"(src) : "memory")
#define CP_COMMIT() asm volatile("cp.async.commit_group;" ::: "memory")
#define CP_WAIT(n)  asm volatile("cp.async.wait_group %0;" :: "n"(n) : "memory")

__global__ __launch_bounds__(256, 6)
void embed_kernel(const int* __restrict__ tokens,
                  const float* __restrict__ W_e,
                  const float* __restrict__ W_p,
                  float* __restrict__ out) {
    __shared__ int   list[CAP];                            // 2KB
    __shared__ __align__(16) float tile[2][ET * SSTRIDE];  // 33.3KB
    __shared__ int   s_cnt;

    int bin   = blockIdx.x % NBINS;
    int eh    = blockIdx.x / NBINS;             // 0..7
    int ebase = eh * (ET * NSUB);               // 128-row span
    int v0    = bin << 8;
    int tid   = threadIdx.x;

    if (tid == 0) s_cnt = 0;

    // ---- Prologue: async-issue tile 0 (overlaps the scan below).
#pragma unroll
    for (int i = 0; i < 4; i++) {
        int idx = tid + 256 * i;
        int r = idx >> 6, c = idx & 63;
        const float* src = W_e + (size_t)(ebase + r) * V + v0 + 4 * c;
        unsigned dst = (unsigned)__cvta_generic_to_shared(&tile[0][r * SSTRIDE + 4 * c]);
        CP_ASYNC16(dst, src);
    }
    CP_COMMIT();
    __syncthreads();                            // s_cnt=0 visible

    // ---- Scan: compact this bin's tokens (hidden under tile-0 fetch).
#pragma unroll
    for (int i = 0; i < 4; i++) {
        int4 tv = __ldg(reinterpret_cast<const int4*>(tokens) + tid + 256 * i);
        int tk0 = (tid + 256 * i) * 4;
        int vv[4] = {tv.x, tv.y, tv.z, tv.w};
#pragma unroll
        for (int k = 0; k < 4; k++) {
            if ((vv[k] >> 8) == bin) {
                int pos = atomicAdd(&s_cnt, 1);
                if (pos < CAP) list[pos] = ((tk0 + k) << 8) | (vv[k] & 255);
            }
        }
    }
    __syncthreads();
    int total = s_cnt;

    if (total <= CAP) {
        // ---- Fast path: 8-subtile double-buffered pipeline.
        int j = tid & 3;                        // float4 slot (16 floats/row)
        int hb = tid >> 2;                      // 64 tokens per pass
#pragma unroll
        for (int t = 0; t < NSUB; t++) {
            if (t < NSUB - 1) {                 // prefetch t+1
#pragma unroll
                for (int i = 0; i < 4; i++) {
                    int idx = tid + 256 * i;
                    int r = idx >> 6, c = idx & 63;
                    const float* src = W_e + (size_t)(ebase + (t + 1) * ET + r) * V + v0 + 4 * c;
                    unsigned dst = (unsigned)__cvta_generic_to_shared(
                        &tile[(t + 1) & 1][r * SSTRIDE + 4 * c]);
                    CP_ASYNC16(dst, src);
                }
                CP_COMMIT();
                CP_WAIT(1);                     // tile t complete
            } else {
                CP_WAIT(0);
            }
            __syncthreads();

            const float* tl = tile[t & 1];
            int e0 = ebase + t * ET;
            for (int h = hb; h < total; h += 64) {
                int packed = list[h];
                int tk = packed >> 8;
                int vl = packed & 255;
                int s  = tk & (S - 1);
                float4 p = __ldg(reinterpret_cast<const float4*>(
                    W_p + (size_t)s * E + e0) + j);
                float4 r;
                r.x = tl[(4 * j + 0) * SSTRIDE + vl] + p.x;
                r.y = tl[(4 * j + 1) * SSTRIDE + vl] + p.y;
                r.z = tl[(4 * j + 2) * SSTRIDE + vl] + p.z;
                r.w = tl[(4 * j + 3) * SSTRIDE + vl] + p.w;
                __stcs(reinterpret_cast<float4*>(out + (size_t)tk * E + e0) + j, r);
            }
            __syncthreads();                    // buf t reusable at t+2 issue
        }
    } else {
        // ---- Fallback (pathological token skew; never hit by this input).
        CP_WAIT(0);
        __syncthreads();
        for (int t = 0; t < NSUB; t++) {
#pragma unroll
            for (int i = 0; i < 4; i++) {
                int idx = tid + 256 * i;
                int r = idx >> 6, c = idx & 63;
                float4 val = __ldg(reinterpret_cast<const float4*>(
                    W_e + (size_t)(ebase + t * ET + r) * V + v0) + c);
                *reinterpret_cast<float4*>(&tile[0][r * SSTRIDE + 4 * c]) = val;
            }
            __syncthreads();
            int e0 = ebase + t * ET;
            for (int idx = tid; idx < NTOK; idx += 256) {
                int v = __ldg(&tokens[idx]);
                if ((v >> 8) == bin) {
                    int vl = v & 255;
                    int s  = idx & (S - 1);
                    for (int rr = 0; rr < ET; rr++)
                        out[(size_t)idx * E + e0 + rr] =
                            tile[0][rr * SSTRIDE + vl] + W_p[(size_t)s * E + e0 + rr];
                }
            }
            __syncthreads();
        }
    }
}

extern "C" void kernel_launch(void* const* d_in, const int* in_sizes, int n_in,
                              void* d_out, int out_size) {
    const int*   tokens = (const int*)d_in[0];
    const float* W_e    = (const float*)d_in[1];
    const float* W_p    = (const float*)d_in[2];
    float*       out    = (float*)d_out;

    embed_kernel<<<NBINS * ESPANS, 256>>>(tokens, W_e, W_p, out);
}

// round 13
// speedup vs baseline: 1.1182x; 1.1182x over previous
#include <cuda_runtime.h>
#include <cuda_bf16.h>

// out[b,s,e] = W_e[e, tokens[b,s]] + W_p[s,e]
// tokens: (2,2048) int32, W_e: (1024,32000) f32, W_p: (2048,1024) f32
// out: (2,2048,1024) f32
//
// Streaming v7. Wave-quantization fix:
// R12 (grid 1000, 888 resident) lost ~44% of its second wave to starvation
// (predicted 56% util -> measured DRAM 50%). R11 (grid 2000) = 90% -> 64%.
// v7 shrinks the work quantum: NSUB=2 (e-span 32), grid = 125 bins x 32
// spans = 4000 blocks -> ~4.5 waves of 888, short tail. Keeps the proven
// cp.async double-buffered tile pipeline + scan-under-prefetch + CAP=512 +
// 6 blocks/SM from R11/R12.

#define B 2
#define S 2048
#define E 1024
#define V 32000
#define NTOK (B * S)       // 4096

#define V_TILE 256
#define NBINS (V / V_TILE) // 125
#define ET 16              // e-rows per subtile
#define NSUB 2             // subtiles per block -> e-span 32
#define ESPANS 32          // 32 spans x 32 = 1024 = E
#define SSTRIDE 260        // 16B-aligned rows -> conflict-free STS/cp.async
#define CAP 512            // hit-list capacity (bin avg ~33; fallback if exceeded)

#define CP_ASYNC16(dst, src) \
    asm volatile("cp.async.cg.shared.global [%0], [%1], 16;" \
                 :: "r"(dst), "l"(src) : "memory")
#define CP_COMMIT() asm volatile("cp.async.commit_group;" ::: "memory")
#define CP_WAIT(n)  asm volatile("cp.async.wait_group %0;" :: "n"(n) : "memory")

__global__ __launch_bounds__(256, 6)
void embed_kernel(const int* __restrict__ tokens,
                  const float* __restrict__ W_e,
                  const float* __restrict__ W_p,
                  float* __restrict__ out) {
    __shared__ int   list[CAP];                            // 2KB
    __shared__ __align__(16) float tile[2][ET * SSTRIDE];  // 33.3KB
    __shared__ int   s_cnt;

    int bin   = blockIdx.x % NBINS;             // fast axis: dense v-sweep
    int eh    = blockIdx.x / NBINS;             // 0..31
    int ebase = eh * (ET * NSUB);               // 32-row span
    int v0    = bin << 8;
    int tid   = threadIdx.x;

    if (tid == 0) s_cnt = 0;

    // ---- Prologue: async-issue tile 0 (overlaps the scan below).
#pragma unroll
    for (int i = 0; i < 4; i++) {
        int idx = tid + 256 * i;
        int r = idx >> 6, c = idx & 63;
        const float* src = W_e + (size_t)(ebase + r) * V + v0 + 4 * c;
        unsigned dst = (unsigned)__cvta_generic_to_shared(&tile[0][r * SSTRIDE + 4 * c]);
        CP_ASYNC16(dst, src);
    }
    CP_COMMIT();
    __syncthreads();                            // s_cnt=0 visible

    // ---- Scan: compact this bin's tokens (hidden under tile-0 fetch).
#pragma unroll
    for (int i = 0; i < 4; i++) {
        int4 tv = __ldg(reinterpret_cast<const int4*>(tokens) + tid + 256 * i);
        int tk0 = (tid + 256 * i) * 4;
        int vv[4] = {tv.x, tv.y, tv.z, tv.w};
#pragma unroll
        for (int k = 0; k < 4; k++) {
            if ((vv[k] >> 8) == bin) {
                int pos = atomicAdd(&s_cnt, 1);
                if (pos < CAP) list[pos] = ((tk0 + k) << 8) | (vv[k] & 255);
            }
        }
    }
    __syncthreads();
    int total = s_cnt;

    if (total <= CAP) {
        // ---- Fast path: 2-subtile double-buffered pipeline.
        int j = tid & 3;                        // float4 slot (16 floats/row)
        int hb = tid >> 2;                      // 64 tokens per pass
#pragma unroll
        for (int t = 0; t < NSUB; t++) {
            if (t < NSUB - 1) {                 // prefetch t+1
#pragma unroll
                for (int i = 0; i < 4; i++) {
                    int idx = tid + 256 * i;
                    int r = idx >> 6, c = idx & 63;
                    const float* src = W_e + (size_t)(ebase + (t + 1) * ET + r) * V + v0 + 4 * c;
                    unsigned dst = (unsigned)__cvta_generic_to_shared(
                        &tile[(t + 1) & 1][r * SSTRIDE + 4 * c]);
                    CP_ASYNC16(dst, src);
                }
                CP_COMMIT();
                CP_WAIT(1);                     // tile t complete
            } else {
                CP_WAIT(0);
            }
            __syncthreads();

            const float* tl = tile[t & 1];
            int e0 = ebase + t * ET;
            for (int h = hb; h < total; h += 64) {
                int packed = list[h];
                int tk = packed >> 8;
                int vl = packed & 255;
                int s  = tk & (S - 1);
                float4 p = __ldg(reinterpret_cast<const float4*>(
                    W_p + (size_t)s * E + e0) + j);
                float4 r;
                r.x = tl[(4 * j + 0) * SSTRIDE + vl] + p.x;
                r.y = tl[(4 * j + 1) * SSTRIDE + vl] + p.y;
                r.z = tl[(4 * j + 2) * SSTRIDE + vl] + p.z;
                r.w = tl[(4 * j + 3) * SSTRIDE + vl] + p.w;
                __stcs(reinterpret_cast<float4*>(out + (size_t)tk * E + e0) + j, r);
            }
            __syncthreads();                    // buf reuse safety
        }
    } else {
        // ---- Fallback (pathological token skew; never hit by this input).
        CP_WAIT(0);
        __syncthreads();
        for (int t = 0; t < NSUB; t++) {
#pragma unroll
            for (int i = 0; i < 4; i++) {
                int idx = tid + 256 * i;
                int r = idx >> 6, c = idx & 63;
                float4 val = __ldg(reinterpret_cast<const float4*>(
                    W_e + (size_t)(ebase + t * ET + r) * V + v0) + c);
                *reinterpret_cast<float4*>(&tile[0][r * SSTRIDE + 4 * c]) = val;
            }
            __syncthreads();
            int e0 = ebase + t * ET;
            for (int idx = tid; idx < NTOK; idx += 256) {
                int v = __ldg(&tokens[idx]);
                if ((v >> 8) == bin) {
                    int vl = v & 255;
                    int s  = idx & (S - 1);
                    for (int rr = 0; rr < ET; rr++)
                        out[(size_t)idx * E + e0 + rr] =
                            tile[0][rr * SSTRIDE + vl] + W_p[(size_t)s * E + e0 + rr];
                }
            }
            __syncthreads();
        }
    }
}

extern "C" void kernel_launch(void* const* d_in, const int* in_sizes, int n_in,
                              void* d_out, int out_size) {
    const int*   tokens = (const int*)d_in[0];
    const float* W_e    = (const float*)d_in[1];
    const float* W_p    = (const float*)d_in[2];
    float*       out    = (float*)d_out;

    embed_kernel<<<NBINS * ESPANS, 256>>>(tokens, W_e, W_p, out);
}

// round 14
// speedup vs baseline: 1.1776x; 1.0531x over previous
#include <cuda_runtime.h>
#include <cuda_bf16.h>

// out[b,s,e] = W_e[e, tokens[b,s]] + W_p[s,e]
// tokens: (2,2048) int32, W_e: (1024,32000) f32, W_p: (2048,1024) f32
// out: (2,2048,1024) f32
//
// Streaming v8: single-wave schedule.
// R11-R13 mapped the trade: more blocks -> redundant token scans (issue 33%
// @4000 blocks); fewer blocks -> wave-quantization tail (50% DRAM @1000
// blocks, 888 resident). v8 eliminates both: grid = 125 bins x 7 = 875
// blocks < 888 resident => exactly ONE wave. Each block scans its bin once
// and streams 9-10 subtiles (16 e-rows x 256 v) through the proven cp.async
// double-buffered pipeline (startup/drain paid once per ~150KB).

#define B 2
#define S 2048
#define E 1024
#define V 32000
#define NTOK (B * S)       // 4096

#define V_TILE 256
#define NBINS (V / V_TILE) // 125
#define ET 16              // e-rows per subtile
#define NTILES 64          // subtiles per bin (E/ET)
#define KPB 7              // blocks per bin -> grid 875 (single wave @ 6/SM)
#define SSTRIDE 260        // 16B-aligned rows -> conflict-free STS/cp.async
#define CAP 512            // hit-list capacity (bin avg ~33; fallback if exceeded)

#define CP_ASYNC16(dst, src) \
    asm volatile("cp.async.cg.shared.global [%0], [%1], 16;" \
                 :: "r"(dst), "l"(src) : "memory")
#define CP_COMMIT() asm volatile("cp.async.commit_group;" ::: "memory")
#define CP_WAIT(n)  asm volatile("cp.async.wait_group %0;" :: "n"(n) : "memory")

__device__ __forceinline__ void issue_tile(const float* __restrict__ W_e,
                                           int tile_row0, int v0, int tid,
                                           float* buf) {
#pragma unroll
    for (int i = 0; i < 4; i++) {
        int idx = tid + 256 * i;
        int r = idx >> 6, c = idx & 63;
        const float* src = W_e + (size_t)(tile_row0 + r) * V + v0 + 4 * c;
        unsigned dst = (unsigned)__cvta_generic_to_shared(&buf[r * SSTRIDE + 4 * c]);
        CP_ASYNC16(dst, src);
    }
    CP_COMMIT();
}

__global__ __launch_bounds__(256, 6)
void embed_kernel(const int* __restrict__ tokens,
                  const float* __restrict__ W_e,
                  const float* __restrict__ W_p,
                  float* __restrict__ out) {
    __shared__ int   list[CAP];                            // 2KB
    __shared__ __align__(16) float tile[2][ET * SSTRIDE];  // 33.3KB
    __shared__ int   s_cnt;

    int bin = blockIdx.x % NBINS;
    int k   = blockIdx.x / NBINS;               // 0..6
    // 64 tiles split 10 + 9*6 across the 7 blocks of this bin.
    int nt  = (k == 0) ? 10 : 9;
    int t0  = (k == 0) ? 0  : 9 * k + 1;
    int v0  = bin << 8;
    int tid = threadIdx.x;

    if (tid == 0) s_cnt = 0;

    // ---- Prologue: async-issue first tile (overlaps the scan below).
    issue_tile(W_e, t0 * ET, v0, tid, tile[0]);
    __syncthreads();                            // s_cnt=0 visible

    // ---- Scan: compact this bin's tokens (once per block, hidden under
    //      the first tile fetch, amortized over 9-10 tiles).
#pragma unroll
    for (int i = 0; i < 4; i++) {
        int4 tv = __ldg(reinterpret_cast<const int4*>(tokens) + tid + 256 * i);
        int tk0 = (tid + 256 * i) * 4;
        int vv[4] = {tv.x, tv.y, tv.z, tv.w};
#pragma unroll
        for (int kk = 0; kk < 4; kk++) {
            if ((vv[kk] >> 8) == bin) {
                int pos = atomicAdd(&s_cnt, 1);
                if (pos < CAP) list[pos] = ((tk0 + kk) << 8) | (vv[kk] & 255);
            }
        }
    }
    __syncthreads();
    int total = s_cnt;

    if (total <= CAP) {
        // ---- Fast path: double-buffered pipeline over nt subtiles.
        int j  = tid & 3;                       // float4 slot (16 floats/row)
        int hb = tid >> 2;                      // 64 tokens per pass
        for (int t = 0; t < nt; t++) {
            if (t < nt - 1) {
                issue_tile(W_e, (t0 + t + 1) * ET, v0, tid, tile[(t + 1) & 1]);
                CP_WAIT(1);                     // tile t complete
            } else {
                CP_WAIT(0);
            }
            __syncthreads();

            const float* tl = tile[t & 1];
            int e0 = (t0 + t) * ET;
            for (int h = hb; h < total; h += 64) {
                int packed = list[h];
                int tk = packed >> 8;
                int vl = packed & 255;
                int s  = tk & (S - 1);
                float4 p = __ldg(reinterpret_cast<const float4*>(
                    W_p + (size_t)s * E + e0) + j);
                float4 r;
                r.x = tl[(4 * j + 0) * SSTRIDE + vl] + p.x;
                r.y = tl[(4 * j + 1) * SSTRIDE + vl] + p.y;
                r.z = tl[(4 * j + 2) * SSTRIDE + vl] + p.z;
                r.w = tl[(4 * j + 3) * SSTRIDE + vl] + p.w;
                __stcs(reinterpret_cast<float4*>(out + (size_t)tk * E + e0) + j, r);
            }
            __syncthreads();                    // buf reuse safety
        }
    } else {
        // ---- Fallback (pathological token skew; never hit by this input).
        CP_WAIT(0);
        __syncthreads();
        for (int t = 0; t < nt; t++) {
            int row0 = (t0 + t) * ET;
#pragma unroll
            for (int i = 0; i < 4; i++) {
                int idx = tid + 256 * i;
                int r = idx >> 6, c = idx & 63;
                float4 val = __ldg(reinterpret_cast<const float4*>(
                    W_e + (size_t)(row0 + r) * V + v0) + c);
                *reinterpret_cast<float4*>(&tile[0][r * SSTRIDE + 4 * c]) = val;
            }
            __syncthreads();
            for (int idx = tid; idx < NTOK; idx += 256) {
                int v = __ldg(&tokens[idx]);
                if ((v >> 8) == bin) {
                    int vl = v & 255;
                    int s  = idx & (S - 1);
                    for (int rr = 0; rr < ET; rr++)
                        out[(size_t)idx * E + row0 + rr] =
                            tile[0][rr * SSTRIDE + vl] + W_p[(size_t)s * E + row0 + rr];
                }
            }
            __syncthreads();
        }
    }
}

extern "C" void kernel_launch(void* const* d_in, const int* in_sizes, int n_in,
                              void* d_out, int out_size) {
    const int*   tokens = (const int*)d_in[0];
    const float* W_e    = (const float*)d_in[1];
    const float* W_p    = (const float*)d_in[2];
    float*       out    = (float*)d_out;

    embed_kernel<<<NBINS * KPB, 256>>>(tokens, W_e, W_p, out);
}

// round 15
// speedup vs baseline: 1.2382x; 1.0515x over previous
#include <cuda_runtime.h>
#include <cuda_bf16.h>

// out[b,s,e] = W_e[e, tokens[b,s]] + W_p[s,e]
// tokens: (2,2048) int32, W_e: (1024,32000) f32, W_p: (2048,1024) f32
// out: (2,2048,1024) f32
//
// Streaming v9: TMA bulk-copy stream.
// R9-R14 pinned the W_e stream at ~4.3-5.1TB/s in every schedule. Measured
// rate == one 16B cp.async issued per SM-cycle => the cap is LSU *issue*,
// not DRAM. v9 moves the stream to cp.async.bulk (UBLKCP): tile rows are
// 1KB contiguous in GMEM, so one 16KB tile = 16 bulk ops (issued by one
// thread) completing on an mbarrier (expect_tx) -- 64x fewer issue ops, copy
// runs on the DMA engine. Keeps R14's single-wave schedule (125 bins x 7
// blocks = 875 < 888 resident), per-block bin scan, double-buffered tiles.

#define B 2
#define S 2048
#define E 1024
#define V 32000
#define NTOK (B * S)       // 4096

#define V_TILE 256
#define NBINS (V / V_TILE) // 125
#define ET 16              // e-rows per subtile
#define KPB 7              // blocks per bin -> grid 875 (single wave @ 6/SM)
#define SSTRIDE 260        // rows 1040B apart: 16B-aligned for bulk dst
#define CAP 512            // hit-list capacity (bin avg ~33; fallback if over)
#define TILE_BYTES (ET * V_TILE * 4)   // 16384

__global__ __launch_bounds__(256, 6)
void embed_kernel(const int* __restrict__ tokens,
                  const float* __restrict__ W_e,
                  const float* __restrict__ W_p,
                  float* __restrict__ out) {
    __shared__ int   list[CAP];                            // 2KB
    __shared__ __align__(16) float tile[2][ET * SSTRIDE];  // 33.3KB
    __shared__ __align__(8) unsigned long long mbar[2];
    __shared__ int   s_cnt;

    int bin = blockIdx.x % NBINS;
    int k   = blockIdx.x / NBINS;               // 0..6
    int nt  = (k == 0) ? 10 : 9;                // 64 tiles split 10 + 9*6
    int t0  = (k == 0) ? 0  : 9 * k + 1;
    int v0  = bin << 8;
    int tid = threadIdx.x;

    unsigned mb0 = (unsigned)__cvta_generic_to_shared(&mbar[0]);
    unsigned mb1 = (unsigned)__cvta_generic_to_shared(&mbar[1]);

    if (tid == 0) {
        s_cnt = 0;
        asm volatile("mbarrier.init.shared.b64 [%0], 1;" :: "r"(mb0));
        asm volatile("mbarrier.init.shared.b64 [%0], 1;" :: "r"(mb1));
        asm volatile("fence.proxy.async.shared::cta;" ::: "memory");
    }
    __syncthreads();                            // init + s_cnt visible

    // ---- Issue tile 0: 16 bulk row-copies (1KB each), one thread.
    if (tid == 0) {
        asm volatile("mbarrier.arrive.expect_tx.shared.b64 _, [%0], %1;"
                     :: "r"(mb0), "r"(TILE_BYTES));
#pragma unroll
        for (int r = 0; r < ET; r++) {
            const float* src = W_e + (size_t)(t0 * ET + r) * V + v0;
            unsigned dst = (unsigned)__cvta_generic_to_shared(
                &tile[0][r * SSTRIDE]);
            asm volatile(
                "cp.async.bulk.shared::cta.global.mbarrier::complete_tx::bytes"
                " [%0], [%1], %2, [%3];"
                :: "r"(dst), "l"(src), "r"(V_TILE * 4), "r"(mb0) : "memory");
        }
    }

    // ---- Scan: compact this bin's tokens (hidden under the tile-0 fetch).
#pragma unroll
    for (int i = 0; i < 4; i++) {
        int4 tv = __ldg(reinterpret_cast<const int4*>(tokens) + tid + 256 * i);
        int tk0 = (tid + 256 * i) * 4;
        int vv[4] = {tv.x, tv.y, tv.z, tv.w};
#pragma unroll
        for (int kk = 0; kk < 4; kk++) {
            if ((vv[kk] >> 8) == bin) {
                int pos = atomicAdd(&s_cnt, 1);
                if (pos < CAP) list[pos] = ((tk0 + kk) << 8) | (vv[kk] & 255);
            }
        }
    }
    __syncthreads();
    int total = s_cnt;

    if (total <= CAP) {
        int j  = tid & 3;                       // float4 slot (16 floats/row)
        int hb = tid >> 2;                      // 64 tokens per pass
        for (int t = 0; t < nt; t++) {
            // Issue tile t+1 into the other buffer (its previous epilogue
            // finished before last iteration's closing __syncthreads).
            if (t < nt - 1 && tid == 0) {
                unsigned mb = ((t + 1) & 1) ? mb1 : mb0;
                asm volatile("mbarrier.arrive.expect_tx.shared.b64 _, [%0], %1;"
                             :: "r"(mb), "r"(TILE_BYTES));
#pragma unroll
                for (int r = 0; r < ET; r++) {
                    const float* src = W_e + (size_t)((t0 + t + 1) * ET + r) * V + v0;
                    unsigned dst = (unsigned)__cvta_generic_to_shared(
                        &tile[(t + 1) & 1][r * SSTRIDE]);
                    asm volatile(
                        "cp.async.bulk.shared::cta.global.mbarrier::complete_tx::bytes"
                        " [%0], [%1], %2, [%3];"
                        :: "r"(dst), "l"(src), "r"(V_TILE * 4), "r"(mb) : "memory");
                }
            }

            // Wait for tile t (buffer t&1, phase (t>>1)&1).
            {
                unsigned mb = (t & 1) ? mb1 : mb0;
                unsigned ph = (t >> 1) & 1;
                unsigned done;
                asm volatile(
                    "{\n\t.reg .pred p;\n\t"
                    "mbarrier.try_wait.parity.shared.b64 p, [%1], %2;\n\t"
                    "selp.b32 %0, 1, 0, p;\n\t}"
                    : "=r"(done) : "r"(mb), "r"(ph) : "memory");
                while (!done) {
                    asm volatile(
                        "{\n\t.reg .pred p;\n\t"
                        "mbarrier.try_wait.parity.shared.b64 p, [%1], %2, 0x989680;\n\t"
                        "selp.b32 %0, 1, 0, p;\n\t}"
                        : "=r"(done) : "r"(mb), "r"(ph) : "memory");
                }
            }

            const float* tl = tile[t & 1];
            int e0 = (t0 + t) * ET;
            for (int h = hb; h < total; h += 64) {
                int packed = list[h];
                int tk = packed >> 8;
                int vl = packed & 255;
                int s  = tk & (S - 1);
                float4 p = __ldg(reinterpret_cast<const float4*>(
                    W_p + (size_t)s * E + e0) + j);
                float4 r;
                r.x = tl[(4 * j + 0) * SSTRIDE + vl] + p.x;
                r.y = tl[(4 * j + 1) * SSTRIDE + vl] + p.y;
                r.z = tl[(4 * j + 2) * SSTRIDE + vl] + p.z;
                r.w = tl[(4 * j + 3) * SSTRIDE + vl] + p.w;
                __stcs(reinterpret_cast<float4*>(out + (size_t)tk * E + e0) + j, r);
            }
            __syncthreads();   // all reads of buffer t done before reissue
        }
    } else {
        // ---- Fallback (pathological token skew; never hit by this input).
        __syncthreads();
        for (int t = 0; t < nt; t++) {
            int row0 = (t0 + t) * ET;
#pragma unroll
            for (int i = 0; i < 4; i++) {
                int idx = tid + 256 * i;
                int r = idx >> 6, c = idx & 63;
                float4 val = __ldg(reinterpret_cast<const float4*>(
                    W_e + (size_t)(row0 + r) * V + v0) + c);
                *reinterpret_cast<float4*>(&tile[1][r * SSTRIDE + 4 * c]) = val;
            }
            __syncthreads();
            for (int idx = tid; idx < NTOK; idx += 256) {
                int v = __ldg(&tokens[idx]);
                if ((v >> 8) == bin) {
                    int vl = v & 255;
                    int s  = idx & (S - 1);
                    for (int rr = 0; rr < ET; rr++)
                        out[(size_t)idx * E + row0 + rr] =
                            tile[1][rr * SSTRIDE + vl] + W_p[(size_t)s * E + row0 + rr];
                }
            }
            __syncthreads();
        }
    }
}

extern "C" void kernel_launch(void* const* d_in, const int* in_sizes, int n_in,
                              void* d_out, int out_size) {
    const int*   tokens = (const int*)d_in[0];
    const float* W_e    = (const float*)d_in[1];
    const float* W_p    = (const float*)d_in[2];
    float*       out    = (float*)d_out;

    embed_kernel<<<NBINS * KPB, 256>>>(tokens, W_e, W_p, out);
}